// round 12
// baseline (speedup 1.0000x reference)
#include <cuda_runtime.h>

// Vanilla tanh RNN: B=512, S=4096, H=40, fp32.
// out = concat( [B*S] per-step fc outputs , [B*H] final hidden )
//
// R12 = R11 + 4-way split of the redundant c-work.
// One warp per batch, one warp per CTA (512 x 32), per-step BAR.SYNC @nw=1.
// a-dot: lane l = row l (20 fma2, unchanged). c-work: lane (s=l>>3, d=l&7)
// computes 10-element partials of row 32+d AND the fc dot (5+5 fma2),
// reduced across the 4-lane group {d,d+8,d+16,d+24} by a 2-level shfl.xor
// butterfly on a packed (row,fc) u64 with add2. fma2/lane: 40 -> 30.
// tanh = MUFU tanh.approx. Lane 8 stores fc z one step behind.

#define BATCH 512
#define SEQ   4096
#define HID   40
#define KCH   64
#define THREADS 32
#define FULLM 0xffffffffu

typedef unsigned long long u64;

__device__ __forceinline__ u64 pack2(float lo, float hi) {
    u64 r;
    asm("mov.b64 %0, {%1, %2};" : "=l"(r) : "f"(lo), "f"(hi));
    return r;
}
__device__ __forceinline__ void unpack2(u64 v, float& lo, float& hi) {
    asm("mov.b64 {%0, %1}, %2;" : "=f"(lo), "=f"(hi) : "l"(v));
}
__device__ __forceinline__ u64 fma2(u64 a, u64 b, u64 c) {
    u64 d;
    asm("fma.rn.f32x2 %0, %1, %2, %3;" : "=l"(d) : "l"(a), "l"(b), "l"(c));
    return d;
}
__device__ __forceinline__ u64 add2(u64 a, u64 b) {
    u64 d;
    asm("add.rn.f32x2 %0, %1, %2;" : "=l"(d) : "l"(a), "l"(b));
    return d;
}
__device__ __forceinline__ void lds2(u64& a, u64& b, unsigned off) {
    asm volatile("ld.shared.v2.u64 {%0, %1}, [%2];"
                 : "=l"(a), "=l"(b) : "r"(off) : "memory");
}
__device__ __forceinline__ u64 lds64(unsigned off) {
    u64 v;
    asm volatile("ld.shared.u64 %0, [%1];" : "=l"(v) : "r"(off) : "memory");
    return v;
}
__device__ __forceinline__ void sts1(unsigned off, float v) {
    asm volatile("st.shared.f32 [%0], %1;" :: "r"(off), "f"(v) : "memory");
}
__device__ __forceinline__ float tanh_mufu(float z) {
    float r;
    asm("tanh.approx.f32 %0, %1;" : "=f"(r) : "f"(z));
    return r;
}

struct Lane {
    u64 wm[HID / 2];      // own row (a-dot), 20 pairs
    u64 wx[5];            // row 32+d, segment s (10 elems)
    u64 wf[5];            // fc_w, segment s
    float wih_m, cb_m;
    float wih_x, cb_x;    // nonzero only on s==0 lanes
    float cb_f;           // fc_b, nonzero only on s==0 lanes
};

// One step: read h from rd, write to wr. Returns fc z (valid in all lanes).
__device__ __forceinline__ float rnn_step(
    unsigned rd, unsigned wr, unsigned seg_off,
    float ia, float ic, float icf, int l,
    const Lane& W, float& hm, float& hxv)
{
    u64 hp[HID / 2];
#pragma unroll
    for (int q = 0; q < HID / 4; q++)
        lds2(hp[2 * q], hp[2 * q + 1], rd + 16u * q);

    u64 hq[5];
#pragma unroll
    for (int j = 0; j < 5; j++)
        hq[j] = lds64(rd + seg_off + 8u * j);

    u64 a0 = pack2(ia, 0.0f);
    u64 c0 = pack2(ic, 0.0f);
    u64 f0 = pack2(icf, 0.0f);
#pragma unroll
    for (int j = 0; j < 5; j++) {
        a0 = fma2(W.wm[4 * j + 0], hp[4 * j + 0], a0);
        c0 = fma2(W.wx[j], hq[j], c0);
        a0 = fma2(W.wm[4 * j + 1], hp[4 * j + 1], a0);
        f0 = fma2(W.wf[j], hq[j], f0);
        a0 = fma2(W.wm[4 * j + 2], hp[4 * j + 2], a0);
        a0 = fma2(W.wm[4 * j + 3], hp[4 * j + 3], a0);
    }
    float clo, chi, flo, fhi;
    unpack2(c0, clo, chi);
    unpack2(f0, flo, fhi);
    u64 pcf = pack2(clo + chi, flo + fhi);   // (row partial, fc partial)

    // butterfly over the 4-lane group {d, d+8, d+16, d+24}
    pcf = add2(pcf, __shfl_xor_sync(FULLM, pcf, 8));
    pcf = add2(pcf, __shfl_xor_sync(FULLM, pcf, 16));

    float alo, ahi;
    unpack2(a0, alo, ahi);
    float zm = alo + ahi;
    float zr, zf;
    unpack2(pcf, zr, zf);       // zr = row 32+d z, zf = fc z (all lanes)

    hm  = tanh_mufu(zm);
    hxv = tanh_mufu(zr);

    sts1(wr + 4u * l, hm);
    if (l < 8) sts1(wr + 4u * (32 + l), hxv);
    return zf;
}

__global__ void __launch_bounds__(THREADS, 8) rnn_kernel(
    const float* __restrict__ x,       // [B, S]
    const float* __restrict__ hidden,  // [B, H]
    const float* __restrict__ w_ih,    // [H]
    const float* __restrict__ w_hh,    // [H, H]
    const float* __restrict__ b_ih,    // [H]
    const float* __restrict__ b_hh,    // [H]
    const float* __restrict__ fc_w,    // [H]
    const float* __restrict__ fc_b,    // [1]
    float* __restrict__ out)           // [B*S] then [B*H]
{
    __shared__ __align__(16) float buf[2][HID];

    const int l  = threadIdx.x;        // one warp per CTA
    const int bg = blockIdx.x;
    const int s  = l >> 3;             // segment 0..3 (10 h-elems each)
    const int d  = l & 7;              // which extra row (32+d)
    const unsigned seg_off = 40u * (unsigned)s;   // byte offset of segment

    Lane W;
#pragma unroll
    for (int j = 0; j < HID / 2; j++)
        W.wm[j] = pack2(w_hh[l * HID + 2 * j], w_hh[l * HID + 2 * j + 1]);

#pragma unroll
    for (int j = 0; j < 5; j++) {
        W.wx[j] = pack2(w_hh[(32 + d) * HID + 10 * s + 2 * j],
                        w_hh[(32 + d) * HID + 10 * s + 2 * j + 1]);
        W.wf[j] = pack2(fc_w[10 * s + 2 * j], fc_w[10 * s + 2 * j + 1]);
    }
    W.wih_m = w_ih[l];
    W.cb_m  = b_ih[l] + b_hh[l];
    W.wih_x = (s == 0) ? w_ih[32 + d] : 0.0f;
    W.cb_x  = (s == 0) ? (b_ih[32 + d] + b_hh[32 + d]) : 0.0f;
    W.cb_f  = (s == 0) ? fc_b[0] : 0.0f;

    // initial state -> buf0
    float hm = hidden[bg * HID + l];
    float hxv = 0.0f;
    buf[0][l] = hm;
    if (l < 8) {
        hxv = hidden[bg * HID + 32 + l];
        buf[0][32 + l] = hxv;
    }
    __syncthreads();

    const unsigned off0 = (unsigned)__cvta_generic_to_shared(&buf[0][0]);
    const unsigned off1 = (unsigned)__cvta_generic_to_shared(&buf[1][0]);

    float xa = x[bg * SEQ + l];
    float xb = x[bg * SEQ + 32 + l];

    for (int chunk = 0; chunk < SEQ / KCH; chunk++) {
        const int t0  = chunk * KCH;
        const int t0n = (chunk + 1 < SEQ / KCH) ? t0 + KCH : 0;
        float xan = x[bg * SEQ + t0n + l];
        float xbn = x[bg * SEQ + t0n + 32 + l];

#pragma unroll 2
        for (int k = 0; k < KCH; k += 2) {
            // hoisted: x broadcast + accumulator inits for BOTH steps
            float xv0 = __shfl_sync(FULLM, (k & 32) ? xb : xa, k & 31);
            float xv1 = __shfl_sync(FULLM, ((k + 1) & 32) ? xb : xa, (k + 1) & 31);
            float ia0 = fmaf(xv0, W.wih_m, W.cb_m);
            float ic0 = fmaf(xv0, W.wih_x, W.cb_x);
            float ia1 = fmaf(xv1, W.wih_m, W.cb_m);
            float ic1 = fmaf(xv1, W.wih_x, W.cb_x);

            // even step: read buf0, write buf1
            __syncthreads();
            float zf0 = rnn_step(off0, off1, seg_off, ia0, ic0, W.cb_f,
                                 l, W, hm, hxv);
            if (l == 8) {
                int ti = t0 + k;
                out[bg * SEQ + (ti ? ti - 1 : 0)] = zf0;
            }
            // odd step: read buf1, write buf0
            __syncthreads();
            float zf1 = rnn_step(off1, off0, seg_off, ia1, ic1, W.cb_f,
                                 l, W, hm, hxv);
            if (l == 8) out[bg * SEQ + t0 + k] = zf1;
        }

        xa = xan;
        xb = xbn;
    }

    // ---- epilogue: out[S-1] = fc . h_{S-1} + fc_b (h in buf0, SEQ even) ----
    __syncthreads();
    {
        u64 hq[5];
#pragma unroll
        for (int j = 0; j < 5; j++)
            hq[j] = lds64(off0 + seg_off + 8u * j);
        u64 f0 = pack2(W.cb_f, 0.0f);
#pragma unroll
        for (int j = 0; j < 5; j++)
            f0 = fma2(W.wf[j], hq[j], f0);
        float flo, fhi;
        unpack2(f0, flo, fhi);
        u64 p = pack2(flo + fhi, 0.0f);
        p = add2(p, __shfl_xor_sync(FULLM, p, 8));
        p = add2(p, __shfl_xor_sync(FULLM, p, 16));
        float zf, dummy;
        unpack2(p, zf, dummy);
        if (l == 8) out[bg * SEQ + SEQ - 1] = zf;
    }

    // ---- final hidden ----
    out[BATCH * SEQ + bg * HID + l] = hm;
    if (l < 8) out[BATCH * SEQ + bg * HID + 32 + l] = hxv;
}

extern "C" void kernel_launch(void* const* d_in, const int* in_sizes, int n_in,
                              void* d_out, int out_size) {
    const float* x      = (const float*)d_in[0];
    const float* hidden = (const float*)d_in[1];
    const float* w_ih   = (const float*)d_in[2];
    const float* w_hh   = (const float*)d_in[3];
    const float* b_ih   = (const float*)d_in[4];
    const float* b_hh   = (const float*)d_in[5];
    const float* fc_w   = (const float*)d_in[6];
    const float* fc_b   = (const float*)d_in[7];
    float* out = (float*)d_out;

    rnn_kernel<<<BATCH, THREADS>>>(x, hidden, w_ih, w_hh, b_ih, b_hh,
                                   fc_w, fc_b, out);
}